// round 8
// baseline (speedup 1.0000x reference)
#include <cuda_runtime.h>

// E[b] = sum over strict-lower-tri pairs (i,j) (row-major flat order):
//          decompFE_flat[b,p] * rsqrt(|coords[b,i]-coords[b,j]|^2)
//
// BPB=2 with PACKED f32x2 math: coords for both batches stored as packed
// (b0,b1) u64 words in smem; lane-resident NEGATED packed j coords so
// dx = add.rn.f32x2. 6 packed FP ops replace 12 scalar ones per iteration.

#define BATCH   2048
#define NATOMS  100
#define NC2     4950
#define TPB     256
#define NWARPS  (TPB / 32)
#define BPB     2

typedef unsigned long long u64;

__device__ __forceinline__ u64 f2_add(u64 a, u64 b) {
    u64 d; asm("add.rn.f32x2 %0, %1, %2;" : "=l"(d) : "l"(a), "l"(b)); return d;
}
__device__ __forceinline__ u64 f2_mul(u64 a, u64 b) {
    u64 d; asm("mul.rn.f32x2 %0, %1, %2;" : "=l"(d) : "l"(a), "l"(b)); return d;
}
__device__ __forceinline__ u64 f2_fma(u64 a, u64 b, u64 c) {
    u64 d; asm("fma.rn.f32x2 %0, %1, %2, %3;" : "=l"(d) : "l"(a), "l"(b), "l"(c)); return d;
}
__device__ __forceinline__ u64 f2_pack(float lo, float hi) {
    return (u64)__float_as_uint(lo) | ((u64)__float_as_uint(hi) << 32);
}

__global__ __launch_bounds__(TPB, 6)
void eij_kernel(const float* __restrict__ coords,
                const float* __restrict__ flat,
                float* __restrict__ out)
{
    // per atom: [x01, y01, z01, pad] packed u64, 32B stride (16B-aligned pairs)
    __shared__ u64   sc[NATOMS * 4];
    __shared__ float warp_part[BPB][NWARPS];

    const int b0   = blockIdx.x * BPB;
    const int t    = threadIdx.x;
    const int lane = t & 31;
    const int wid  = t >> 5;

    // stage packed coords
    for (int k = t; k < NATOMS * 3; k += TPB) {
        const int a = k / 3, c = k - a * 3;
        float v0 = coords[(size_t)b0 * (NATOMS * 3) + k];
        float v1 = coords[(size_t)(b0 + 1) * (NATOMS * 3) + k];
        sc[a * 4 + c] = f2_pack(v0, v1);
    }
    __syncthreads();

    const float* fb = flat + (size_t)b0 * NC2;

    float acc0 = 0.0f, acc1 = 0.0f;
    const u64 SGN = 0x8000000080000000ULL;

    #pragma unroll
    for (int jb = 0; jb < 4; ++jb) {
        const int jbase = jb * 32;
        const int j = jbase + lane;

        // lane-resident negated packed j coords
        u64 nxj = 0, nyj = 0, nzj = 0;
        if (j < NATOMS) {
            nxj = sc[j * 4 + 0] ^ SGN;
            nyj = sc[j * 4 + 1] ^ SGN;
            nzj = sc[j * 4 + 2] ^ SGN;
        }

        int i   = jbase + 1 + wid;
        int off = i * (i - 1) / 2 + jbase + lane;

        #pragma unroll 4
        for (; i < NATOMS; i += NWARPS, off += 8 * i - 36) {
            const bool valid = lane < (i - jbase);

            float v0 = 0.0f, v1 = 0.0f;
            if (valid) {
                const float* p = fb + off;
                v0 = __ldcs(p);
                v1 = __ldcs(p + NC2);
            }

            // warp-uniform packed i coords
            const u64 xi = sc[i * 4 + 0];
            const u64 yi = sc[i * 4 + 1];
            const u64 zi = sc[i * 4 + 2];

            const u64 dx = f2_add(xi, nxj);
            const u64 dy = f2_add(yi, nyj);
            const u64 dz = f2_add(zi, nzj);
            const u64 r2 = f2_fma(dx, dx, f2_fma(dy, dy, f2_mul(dz, dz)));

            const float r20 = __uint_as_float((unsigned)(r2 & 0xFFFFFFFFULL));
            const float r21 = __uint_as_float((unsigned)(r2 >> 32));

            if (valid) {
                acc0 = fmaf(v0, rsqrtf(r20), acc0);
                acc1 = fmaf(v1, rsqrtf(r21), acc1);
            }
        }
    }

    // reductions
    #pragma unroll
    for (int off = 16; off > 0; off >>= 1) {
        acc0 += __shfl_down_sync(0xFFFFFFFFu, acc0, off);
        acc1 += __shfl_down_sync(0xFFFFFFFFu, acc1, off);
    }
    if (lane == 0) { warp_part[0][wid] = acc0; warp_part[1][wid] = acc1; }
    __syncthreads();

    if (wid == 0 && lane < NWARPS) {
        float s0 = warp_part[0][lane];
        float s1 = warp_part[1][lane];
        #pragma unroll
        for (int off = NWARPS / 2; off > 0; off >>= 1) {
            s0 += __shfl_down_sync(0xFFu, s0, off);
            s1 += __shfl_down_sync(0xFFu, s1, off);
        }
        if (lane == 0) { out[b0] = s0; out[b0 + 1] = s1; }
    }
}

extern "C" void kernel_launch(void* const* d_in, const int* in_sizes, int n_in,
                              void* d_out, int out_size)
{
    const float* coords = (const float*)d_in[0];   // [2048, 100, 3]
    const float* flat   = (const float*)d_in[1];   // [2048, 4950]
    float* out          = (float*)d_out;           // [2048, 1]

    eij_kernel<<<BATCH / BPB, TPB>>>(coords, flat, out);
}